// round 8
// baseline (speedup 1.0000x reference)
#include <cuda_runtime.h>
#include <cstdint>

// Problem constants
#define T_ALL   32
#define B_BINS  32
#define G_MAX   64

#define TB      16                   // t-values per CTA (items processed 2x, not 4x)
#define TBLKS   (T_ALL / TB)         // 2
#define CHUNKS  74                   // 2*74 = 148 CTAs = 1 CTA/SM, co-resident
#define NBLOCKS (TBLKS * CHUNKS)     // 148
#define MAIN_THREADS 512

#define SM_CELLS (G_MAX * B_BINS * TB)      // 32768
#define SMEM_BYTES (SM_CELLS * 4)           // 128 KB

// z = 200*(lin_b - h) = b*D - H,  H = 200h + 220,  D = 440/31
// Window |z| < 4.5: width 9 < D => at most ONE transition bin per (item,t).
#define DH_STEP  7.0967742f          // D/2
#define ZH_CUT   2.25f
#define FB_MUL   14.0909091f         // 200*31/440
#define FB_ADD   15.8170455f         // (220+4.5)*31/440
#define MAGIC_F  12582912.0f         // 2^23 + 2^22
#define MAGIC_I  0x4B400000

// Per-CTA partial differentials (Q16.16 in u32, two's-complement wrap OK).
// Fully overwritten every launch -> graph-replay safe without zeroing.
__device__ __align__(16) unsigned int g_part[NBLOCKS][SM_CELLS];  // 19.4 MB
__device__ unsigned int bar_a = 0;   // grid barrier arrivals
__device__ unsigned int bar_b = 0;   // post-phase-2 arrivals (for reset)

static __device__ __forceinline__ float tanh_approx(float x) {
    float y;
    asm("tanh.approx.f32 %0, %1;" : "=f"(y) : "f"(x));
    return y;
}
static __device__ __forceinline__ int f2i_rn_magic(float x) {
    return __float_as_int(x + MAGIC_F) - MAGIC_I;
}

// ---------------------------------------------------------------------------
// Single fused persistent kernel.
// Phase 1: per-(item,t) differentials into SMEM [tt][g][b] with WARP-AGGREGATED
//          integer atomics (match_any + redux -> one atomic pair per (g,b_sat)
//          group). Differential semantics per item:
//            acc[b_sat-1] += sgn*q ;  acc[b_sat] += sgn*65536 - sgn*q
//          so prefix over b yields sgn*q at b_sat-1 and sgn*65536 beyond.
// Grid barrier (148 co-resident CTAs). Phase 2: warp per (g,t), sum 74 chunk
// partials, warp-scan over b, emit.
// ---------------------------------------------------------------------------
__global__ void __launch_bounds__(MAIN_THREADS, 1)
ect_fused_kernel(const float* __restrict__ x, const float* __restrict__ v,
                 const int* __restrict__ ei, const int* __restrict__ batch,
                 int N, int E, float* __restrict__ out)
{
    extern __shared__ unsigned int s_acc[];

    const int tblk  = blockIdx.x / CHUNKS;
    const int chunk = blockIdx.x - tblk * CHUNKS;
    const int t0    = tblk * TB;
    const int tid   = threadIdx.x;
    const int lane  = tid & 31;

    {   // vectorized zero: 32768 u32 = 8192 uint4
        uint4* s4 = reinterpret_cast<uint4*>(s_acc);
        for (int i = tid; i < SM_CELLS / 4; i += MAIN_THREADS)
            s4[i] = make_uint4(0u, 0u, 0u, 0u);
    }

    float v0[TB], v1[TB], v2[TB];
#pragma unroll
    for (int tt = 0; tt < TB; ++tt) {
        v0[tt] = __ldg(&v[0 * T_ALL + t0 + tt]);
        v1[tt] = __ldg(&v[1 * T_ALL + t0 + tt]);
        v2[tt] = __ldg(&v[2 * T_ALL + t0 + tt]);
    }
    __syncthreads();

    // Uniform trip-count item loop (tail lanes clamp loads, contribute 0) so
    // warp collectives below never diverge.
    const int total = N + E;
    for (int base = chunk * MAIN_THREADS; base < total;
         base += CHUNKS * MAIN_THREADS) {
        const int  i     = base + tid;
        const bool valid = (i < total);
        const int  ic    = valid ? i : (total - 1);

        float a0, a1, a2, c0 = 0.f, c1 = 0.f, c2 = 0.f;
        int g;
        const bool isEdge = (ic >= N);
        if (!isEdge) {
            a0 = __ldg(&x[3 * ic]); a1 = __ldg(&x[3 * ic + 1]); a2 = __ldg(&x[3 * ic + 2]);
            g  = __ldg(&batch[ic]);
        } else {
            const int e = ic - N;
            const int s = __ldg(&ei[e]);
            const int d = __ldg(&ei[E + e]);
            g  = __ldg(&batch[s]);
            a0 = __ldg(&x[3 * s]); a1 = __ldg(&x[3 * s + 1]); a2 = __ldg(&x[3 * s + 2]);
            c0 = __ldg(&x[3 * d]); c1 = __ldg(&x[3 * d + 1]); c2 = __ldg(&x[3 * d + 2]);
        }
        // sgnv: +1 node, -1 edge, 0 invalid tail lane
        const int sgnv = valid ? (isEdge ? -1 : 1) : 0;
        const int satv = sgnv << 16;                   // sgn * 65536

#pragma unroll
        for (int tt = 0; tt < TB; ++tt) {
            float h = fmaf(a2, v2[tt], fmaf(a1, v1[tt], a0 * v0[tt]));
            if (isEdge) {
                float h2 = fmaf(c2, v2[tt], fmaf(c1, v1[tt], c0 * v0[tt]));
                h = fmaxf(h, h2);
            }
            // b_sat = clamp(ceil((H+ZCUT)/D), 0, 32) via magic round
            float fb = fmaf(h, FB_MUL, FB_ADD);
            fb = fminf(fmaxf(fb, -0.4f), 31.9f);
            const float tmag  = (fb + 0.5f) + MAGIC_F;
            const int   b_sat = __float_as_int(tmag) - MAGIC_I;   // [0,32]
            const float blof  = tmag - MAGIC_F;
            // z/2 at transition bin b_sat-1 (true h, not clamped)
            const float zh = fmaf(blof, DH_STEP,
                                  fmaf(h, -100.0f, -110.0f - DH_STEP));

            int q = 0;
            if (zh > -ZH_CUT && b_sat >= 1)
                q = f2i_rn_magic(fmaf(tanh_approx(zh), 32768.0f, 32768.0f));
            const int qs = q * sgnv;

            // ---- warp aggregation: one atomic pair per (g,b_sat) group ----
            const int key = (g << 6) | b_sat;
            const unsigned grp = __match_any_sync(0xFFFFFFFFu, key);
            const int sum_q = __reduce_add_sync(grp, qs);    // -> bin b_sat-1
            const int sum_s = __reduce_add_sync(grp, satv);  // total sat mass
            if (__ffs(grp) == lane + 1) {              // lowest-lane leader
                unsigned int* accp = s_acc + tt * (G_MAX * B_BINS) + g * B_BINS;
                if (b_sat >= 1 && sum_q != 0)
                    atomicAdd(accp + (b_sat - 1), (unsigned int)sum_q);
                const int rem = sum_s - sum_q;         // differential at b_sat
                if (b_sat < B_BINS && rem != 0)
                    atomicAdd(accp + b_sat, (unsigned int)rem);
            }
        }
    }

    __syncthreads();

    // Flush: plain vectorized stores to this CTA's private slab (no atomics).
    {
        uint4* dst = reinterpret_cast<uint4*>(g_part[blockIdx.x]);
        const uint4* s4 = reinterpret_cast<const uint4*>(s_acc);
        for (int i = tid; i < SM_CELLS / 4; i += MAIN_THREADS)
            dst[i] = s4[i];
    }
    __syncthreads();

    // ---- grid-wide barrier (all 148 CTAs co-resident: 1 CTA/SM) ----
    if (tid == 0) {
        unsigned int old;
        asm volatile("atom.add.release.gpu.u32 %0, [%1], %2;"
                     : "=r"(old) : "l"(&bar_a), "r"(1u) : "memory");
        unsigned int seen;
        do {
            asm volatile("ld.acquire.gpu.u32 %0, [%1];"
                         : "=r"(seen) : "l"(&bar_a) : "memory");
            if (seen >= (unsigned)NBLOCKS) break;
            __nanosleep(64);
        } while (true);
    }
    __syncthreads();

    // ---- Phase 2: warp per (g,t). lane = b. Need 2048 warps; have 2368.
    const int gw = blockIdx.x * (MAIN_THREADS / 32) + (tid >> 5);
    if (gw < G_MAX * T_ALL) {
        const int g     = gw >> 5;
        const int t     = gw & 31;
        const int ptblk = t / TB;
        const int ptt   = t % TB;
        const int off   = ptt * (G_MAX * B_BINS) + g * B_BINS + lane;

        int s = 0;
#pragma unroll 8
        for (int c = 0; c < CHUNKS; ++c)
            s += (int)__ldcg(&g_part[ptblk * CHUNKS + c][off]);

#pragma unroll
        for (int o = 1; o < 32; o <<= 1) {
            const int nb = __shfl_up_sync(0xFFFFFFFFu, s, o);
            if (lane >= o) s += nb;
        }
        out[g * (B_BINS * T_ALL) + lane * T_ALL + t] = (float)s * (1.0f / 65536.0f);
    }

    // ---- reset barrier counters for the next graph replay ----
    __syncthreads();
    if (tid == 0) {
        const unsigned int old = atomicAdd(&bar_b, 1u);
        if (old == (unsigned)(NBLOCKS - 1)) {   // everyone passed bar_a spin
            bar_a = 0u;
            bar_b = 0u;
        }
    }
}

// ---------------------------------------------------------------------------
extern "C" void kernel_launch(void* const* d_in, const int* in_sizes, int n_in,
                              void* d_out, int out_size)
{
    const float* x     = (const float*)d_in[0];
    const float* v     = (const float*)d_in[1];
    const int*   ei    = (const int*)d_in[3];
    const int*   batch = (const int*)d_in[4];

    const int N = in_sizes[4];
    const int E = in_sizes[3] / 2;

    cudaFuncSetAttribute(ect_fused_kernel,
                         cudaFuncAttributeMaxDynamicSharedMemorySize, SMEM_BYTES);

    ect_fused_kernel<<<NBLOCKS, MAIN_THREADS, SMEM_BYTES>>>(
        x, v, ei, batch, N, E, (float*)d_out);
}

// round 9
// speedup vs baseline: 9.4399x; 9.4399x over previous
#include <cuda_runtime.h>
#include <cstdint>

// Problem constants
#define T_ALL   32
#define B_BINS  32
#define G_MAX   64

#define TB      16                   // t-values per CTA: items gathered 2x total (was 4x)
#define TBLKS   (T_ALL / TB)         // 2
#define CHUNKS  74                   // 2*74 = 148 CTAs = 1 CTA/SM, co-resident
#define NBLOCKS (TBLKS * CHUNKS)     // 148
#define MAIN_THREADS 512

#define SM_CELLS (G_MAX * B_BINS * TB)      // 32768
#define SMEM_BYTES (SM_CELLS * 4)           // 128 KB -> exactly 1 CTA/SM

// z = 200*(lin_b - h) = b*D - H,  H = 200h + 220,  D = 440/31
// Window |z| < 4.5: width 9 < D => at most ONE transition bin per (item,t).
#define DH_STEP  7.0967742f          // D/2
#define ZH_CUT   2.25f
#define FB_MUL   14.0909091f         // 200*31/440
#define FB_ADD   15.8170455f         // (220+4.5)*31/440
#define MAGIC_F  12582912.0f         // 2^23 + 2^22
#define MAGIC_I  0x4B400000

// Per-CTA partial differentials (Q16.16 in u32, two's-complement wrap OK).
// Fully overwritten every launch -> graph-replay safe without zeroing.
__device__ __align__(16) unsigned int g_part[NBLOCKS][SM_CELLS];  // 19.4 MB
__device__ unsigned int bar_a = 0;   // grid barrier arrivals
__device__ unsigned int bar_b = 0;   // post-phase-2 arrivals (for reset)

static __device__ __forceinline__ float tanh_approx(float x) {
    float y;
    asm("tanh.approx.f32 %0, %1;" : "=f"(y) : "f"(x));
    return y;
}
static __device__ __forceinline__ int f2i_rn_magic(float x) {
    return __float_as_int(x + MAGIC_F) - MAGIC_I;
}

// ---------------------------------------------------------------------------
// Single fused persistent kernel (plain smem atomics -- NO warp collectives).
// Phase 1: per-(item,t) differentials into SMEM [tt][g][b]:
//            acc[b_sat-1] += sgn*q ;  acc[b_sat] += sgn*(65536 - q)
// Grid barrier (148 co-resident CTAs). Phase 2: warp per (g,t), sum 74 chunk
// partials, warp-scan over b, emit.
// ---------------------------------------------------------------------------
__global__ void __launch_bounds__(MAIN_THREADS, 1)
ect_fused_kernel(const float* __restrict__ x, const float* __restrict__ v,
                 const int* __restrict__ ei, const int* __restrict__ batch,
                 int N, int E, float* __restrict__ out)
{
    extern __shared__ unsigned int s_acc[];

    const int tblk  = blockIdx.x / CHUNKS;
    const int chunk = blockIdx.x - tblk * CHUNKS;
    const int t0    = tblk * TB;
    const int tid   = threadIdx.x;

    {   // vectorized zero: 32768 u32 = 8192 uint4
        uint4* s4 = reinterpret_cast<uint4*>(s_acc);
        for (int i = tid; i < SM_CELLS / 4; i += MAIN_THREADS)
            s4[i] = make_uint4(0u, 0u, 0u, 0u);
    }

    float v0[TB], v1[TB], v2[TB];
#pragma unroll
    for (int tt = 0; tt < TB; ++tt) {
        v0[tt] = __ldg(&v[0 * T_ALL + t0 + tt]);
        v1[tt] = __ldg(&v[1 * T_ALL + t0 + tt]);
        v2[tt] = __ldg(&v[2 * T_ALL + t0 + tt]);
    }
    __syncthreads();

    // Strided-block item loop: CTA takes contiguous 512-item slices at stride
    // CHUNKS*512 -> coalesced index loads, even node/edge mix per CTA.
    const int total = N + E;
    for (int i = chunk * MAIN_THREADS + tid; i < total;
         i += CHUNKS * MAIN_THREADS) {
        float a0, a1, a2, c0 = 0.f, c1 = 0.f, c2 = 0.f;
        int g;
        const bool isEdge = (i >= N);
        if (!isEdge) {
            a0 = __ldg(&x[3 * i]); a1 = __ldg(&x[3 * i + 1]); a2 = __ldg(&x[3 * i + 2]);
            g  = __ldg(&batch[i]);
        } else {
            const int e = i - N;
            const int s = __ldg(&ei[e]);
            const int d = __ldg(&ei[E + e]);
            g  = __ldg(&batch[s]);
            a0 = __ldg(&x[3 * s]); a1 = __ldg(&x[3 * s + 1]); a2 = __ldg(&x[3 * s + 2]);
            c0 = __ldg(&x[3 * d]); c1 = __ldg(&x[3 * d + 1]); c2 = __ldg(&x[3 * d + 2]);
        }
        const int sgn = isEdge ? -1 : 1;
        unsigned int* accg = s_acc + g * B_BINS;

#pragma unroll
        for (int tt = 0; tt < TB; ++tt) {
            float h = fmaf(a2, v2[tt], fmaf(a1, v1[tt], a0 * v0[tt]));
            if (isEdge) {
                float h2 = fmaf(c2, v2[tt], fmaf(c1, v1[tt], c0 * v0[tt]));
                h = fmaxf(h, h2);
            }
            // b_sat = clamp(ceil((H+ZCUT)/D), 0, 32) via magic round
            float fb = fmaf(h, FB_MUL, FB_ADD);
            fb = fminf(fmaxf(fb, -0.4f), 31.9f);
            const float tmag  = (fb + 0.5f) + MAGIC_F;
            const int   b_sat = __float_as_int(tmag) - MAGIC_I;   // [0,32]
            const float blof  = tmag - MAGIC_F;
            // z/2 at transition bin b_sat-1 (true h, not clamped)
            const float zh = fmaf(blof, DH_STEP,
                                  fmaf(h, -100.0f, -110.0f - DH_STEP));

            unsigned int* accp = accg + tt * (G_MAX * B_BINS);
            int q = 0;
            if (zh > -ZH_CUT && b_sat >= 1) {
                const float sg = fmaf(tanh_approx(zh), 32768.0f, 32768.0f);
                q = f2i_rn_magic(sg);
                atomicAdd(accp + (b_sat - 1), (unsigned int)(sgn * q));
            }
            if (b_sat < B_BINS)
                atomicAdd(accp + b_sat, (unsigned int)(sgn * (65536 - q)));
        }
    }

    __syncthreads();

    // Flush: plain vectorized stores to this CTA's private slab (no atomics).
    {
        uint4* dst = reinterpret_cast<uint4*>(g_part[blockIdx.x]);
        const uint4* s4 = reinterpret_cast<const uint4*>(s_acc);
        for (int i = tid; i < SM_CELLS / 4; i += MAIN_THREADS)
            dst[i] = s4[i];
    }
    __syncthreads();

    // ---- grid-wide barrier (all 148 CTAs co-resident: 1 CTA/SM) ----
    if (tid == 0) {
        unsigned int old;
        asm volatile("atom.add.release.gpu.u32 %0, [%1], %2;"
                     : "=r"(old) : "l"(&bar_a), "r"(1u) : "memory");
        unsigned int seen;
        do {
            asm volatile("ld.acquire.gpu.u32 %0, [%1];"
                         : "=r"(seen) : "l"(&bar_a) : "memory");
            if (seen >= (unsigned)NBLOCKS) break;
            __nanosleep(64);
        } while (true);
    }
    __syncthreads();

    // ---- Phase 2: warp per (g,t). lane = b. Need 2048 warps; have 2368.
    const int lane = tid & 31;
    const int gw   = blockIdx.x * (MAIN_THREADS / 32) + (tid >> 5);
    if (gw < G_MAX * T_ALL) {
        const int g     = gw >> 5;
        const int t     = gw & 31;
        const int ptblk = t / TB;
        const int ptt   = t % TB;
        const int off   = ptt * (G_MAX * B_BINS) + g * B_BINS + lane;

        int s = 0;
#pragma unroll 8
        for (int c = 0; c < CHUNKS; ++c)
            s += (int)__ldcg(&g_part[ptblk * CHUNKS + c][off]);

#pragma unroll
        for (int o = 1; o < 32; o <<= 1) {
            const int nb = __shfl_up_sync(0xFFFFFFFFu, s, o);
            if (lane >= o) s += nb;
        }
        out[g * (B_BINS * T_ALL) + lane * T_ALL + t] = (float)s * (1.0f / 65536.0f);
    }

    // ---- reset barrier counters for the next graph replay ----
    __syncthreads();
    if (tid == 0) {
        const unsigned int old = atomicAdd(&bar_b, 1u);
        if (old == (unsigned)(NBLOCKS - 1)) {   // everyone passed bar_a spin
            bar_a = 0u;
            bar_b = 0u;
        }
    }
}

// ---------------------------------------------------------------------------
extern "C" void kernel_launch(void* const* d_in, const int* in_sizes, int n_in,
                              void* d_out, int out_size)
{
    const float* x     = (const float*)d_in[0];
    const float* v     = (const float*)d_in[1];
    const int*   ei    = (const int*)d_in[3];
    const int*   batch = (const int*)d_in[4];

    const int N = in_sizes[4];
    const int E = in_sizes[3] / 2;

    cudaFuncSetAttribute(ect_fused_kernel,
                         cudaFuncAttributeMaxDynamicSharedMemorySize, SMEM_BYTES);

    ect_fused_kernel<<<NBLOCKS, MAIN_THREADS, SMEM_BYTES>>>(
        x, v, ei, batch, N, E, (float*)d_out);
}